// round 9
// baseline (speedup 1.0000x reference)
#include <cuda_runtime.h>
#include <cuda_fp16.h>
#include <stdint.h>

// Problem constants (fixed by the dataset)
#define IN_F   1024
#define OUT_F  256
#define NROWS_MAX 100000
#define CAP    64           // max nnz per row; Poisson(10) => P(>64) ~ 0

// ---------------- scratch (__device__ globals; no allocations allowed) ------
__device__ int      g_count[NROWS_MAX];
__device__ unsigned g_bucket[(size_t)NROWS_MAX * CAP];   // (col<<16) | fp16(val)
// Wt[IN][OUT] fp16 as half2-words. Row = 128 uints = 512B, 128B-aligned so each
// 64-col slice chunk is exactly one cache line. Slice s of col c = lines
// [c*128 + s*32, +32) -> per-pass footprint = 1024 lines = 128KB (L1-resident).
__device__ __align__(128) unsigned g_wt_h[IN_F * OUT_F / 2];

// ---------------- kernel 1: transpose+convert W -> fp16, fused counter zero -
// 16x16 tiles, 1024 blocks of 256 threads: enough CTAs to hide latency.
__global__ void __launch_bounds__(256) transpose_kernel(const float* __restrict__ W,
                                                        int n_rows) {
    __shared__ float tile[16][17];
    int tx = threadIdx.x, ty = threadIdx.y;   // both 0..15

    // fused: zero per-row counters (262144 threads cover 100k)
    int flat = ((blockIdx.y * gridDim.x + blockIdx.x) << 8) + (ty << 4) + tx;
    if (flat < n_rows) g_count[flat] = 0;

    int x = blockIdx.x * 16 + tx;   // IN index (fast dim of W)
    int y = blockIdx.y * 16 + ty;   // OUT index
    tile[ty][tx] = W[y * IN_F + x];
    __syncthreads();
    int c = blockIdx.x * 16 + ty;   // IN index (row of Wt)
    int o = blockIdx.y * 16 + tx;   // OUT index (fast dim of Wt)
    ((__half*)g_wt_h)[c * OUT_F + o] = __float2half_rn(tile[tx][ty]);
}

// ---------------- kernel 2: scatter nnz into per-row buckets (x4, 4B entries)
__device__ __forceinline__ unsigned pack_entry(int col, float v) {
    return ((unsigned)col << 16) |
           (unsigned)__half_as_ushort(__float2half_rn(v));
}

__global__ void scatter_kernel(const int* __restrict__ rows,
                               const int* __restrict__ cols,
                               const float* __restrict__ vals,
                               int nnz) {
    int t = blockIdx.x * blockDim.x + threadIdx.x;
    int base = t * 4;
    if (base + 3 < nnz) {
        int4   r4 = ((const int4*)rows)[t];
        int4   c4 = ((const int4*)cols)[t];
        float4 v4 = ((const float4*)vals)[t];
        int r, s;
        r = r4.x; s = atomicAdd(&g_count[r], 1);
        if (s < CAP) g_bucket[(size_t)r * CAP + s] = pack_entry(c4.x, v4.x);
        r = r4.y; s = atomicAdd(&g_count[r], 1);
        if (s < CAP) g_bucket[(size_t)r * CAP + s] = pack_entry(c4.y, v4.y);
        r = r4.z; s = atomicAdd(&g_count[r], 1);
        if (s < CAP) g_bucket[(size_t)r * CAP + s] = pack_entry(c4.z, v4.z);
        r = r4.w; s = atomicAdd(&g_count[r], 1);
        if (s < CAP) g_bucket[(size_t)r * CAP + s] = pack_entry(c4.w, v4.w);
    } else {
        for (int i = base; i < nnz; ++i) {
            int r = rows[i];
            int s = atomicAdd(&g_count[r], 1);
            if (s < CAP) g_bucket[(size_t)r * CAP + s] = pack_entry(cols[i], vals[i]);
        }
    }
}

// unpack broadcast entry -> (weight word, half2{v,v}) and accumulate
__device__ __forceinline__ void nnz_acc(unsigned e, const unsigned* __restrict__ wl,
                                        __half2& acc) {
    unsigned col = e >> 16;
    unsigned hv  = __byte_perm(e, 0, 0x1010);   // replicate low half -> {v,v}
    unsigned w   = wl[col << 7];                 // col*128 uints; L1-resident line
    acc = __hfma2(*(const __half2*)&hv, *(const __half2*)&w, acc);
}

// ---------------- kernel 3: 4 column-slice passes, one warp per row ---------
// blockIdx.y = pass (slice of 64 output cols). Blocks dispatch x-fastest, so
// passes execute ~sequentially: per-SM weight working set = 128KB = L1-resident.
// Bucket/count loads use .cg (L2-only) so they never evict weight lines.
__global__ void __launch_bounds__(256) spmm_kernel(const float* __restrict__ bias,
                                                   float* __restrict__ out,
                                                   int n_rows) {
    int pass  = blockIdx.y;
    int gwarp = (blockIdx.x * blockDim.x + threadIdx.x) >> 5;
    int lane  = threadIdx.x & 31;
    if (gwarp >= n_rows) return;
    int r = gwarp;

    int cnt = __ldcg(&g_count[r]);
    if (cnt > CAP) cnt = CAP;
    const unsigned* bk = g_bucket + (size_t)r * CAP;

    // preload up to 32 packed entries (L2-only load), broadcast via shfl
    unsigned my = 0u;
    if (lane < cnt) my = __ldcg(&bk[lane]);

    __half2 acc = __float2half2_rn(0.f);
    // lane owns half2-word (pass*32 + lane) of each weight row = cols [2u, 2u+1]
    const unsigned* wl = g_wt_h + (pass << 5) + lane;

    int n0 = cnt < 32 ? cnt : 32;
    int j = 0;
    #pragma unroll 1
    for (; j + 4 <= n0; j += 4) {
        unsigned e0 = __shfl_sync(0xffffffffu, my, j);
        unsigned e1 = __shfl_sync(0xffffffffu, my, j + 1);
        unsigned e2 = __shfl_sync(0xffffffffu, my, j + 2);
        unsigned e3 = __shfl_sync(0xffffffffu, my, j + 3);
        // independent loads first for MLP
        unsigned w0 = wl[(e0 >> 16) << 7];
        unsigned w1 = wl[(e1 >> 16) << 7];
        unsigned w2 = wl[(e2 >> 16) << 7];
        unsigned w3 = wl[(e3 >> 16) << 7];
        unsigned v0 = __byte_perm(e0, 0, 0x1010);
        unsigned v1 = __byte_perm(e1, 0, 0x1010);
        unsigned v2 = __byte_perm(e2, 0, 0x1010);
        unsigned v3 = __byte_perm(e3, 0, 0x1010);
        acc = __hfma2(*(const __half2*)&v0, *(const __half2*)&w0, acc);
        acc = __hfma2(*(const __half2*)&v1, *(const __half2*)&w1, acc);
        acc = __hfma2(*(const __half2*)&v2, *(const __half2*)&w2, acc);
        acc = __hfma2(*(const __half2*)&v3, *(const __half2*)&w3, acc);
    }
    #pragma unroll 1
    for (; j < n0; ++j) {
        unsigned e = __shfl_sync(0xffffffffu, my, j);
        nnz_acc(e, wl, acc);
    }
    // rare tail (cnt > 32): direct L2 loads
    #pragma unroll 1
    for (int t = 32; t < cnt; ++t) {
        unsigned e = __ldcg(&bk[t]);
        nnz_acc(e, wl, acc);
    }

    // epilogue: fp32 bias add + store of this slice's 2 cols per lane
    int u = (pass << 5) + lane;                 // half2-word index in the row
    float2 f = __half22float2(acc);
    float2 bb = ((const float2*)bias)[u];
    f.x += bb.x;
    f.y += bb.y;
    ((float2*)(out + (size_t)r * OUT_F))[u] = f;
}

// ---------------- launcher ---------------------------------------------------
extern "C" void kernel_launch(void* const* d_in, const int* in_sizes, int n_in,
                              void* d_out, int out_size) {
    const int*   rows   = (const int*)  d_in[0];
    const int*   cols   = (const int*)  d_in[1];
    const float* vals   = (const float*)d_in[2];
    // d_in[3] = n_rows scalar (unused; derive from out_size)
    const float* weight = (const float*)d_in[4];
    const float* bias   = (const float*)d_in[5];

    int nnz    = in_sizes[0];
    int n_rows = out_size / OUT_F;

    transpose_kernel<<<dim3(IN_F / 16, OUT_F / 16), dim3(16, 16)>>>(weight, n_rows);

    int sthreads = (nnz + 3) / 4;
    scatter_kernel<<<(sthreads + 255) / 256, 256>>>(rows, cols, vals, nnz);

    int warps_per_block = 256 / 32;
    int blocks_x = (n_rows + warps_per_block - 1) / warps_per_block;
    spmm_kernel<<<dim3(blocks_x, 4), 256>>>(bias, (float*)d_out, n_rows);
}

// round 10
// speedup vs baseline: 1.7872x; 1.7872x over previous
#include <cuda_runtime.h>
#include <cuda_fp16.h>
#include <stdint.h>

// Problem constants (fixed by the dataset)
#define IN_F   1024
#define OUT_F  256
#define NROWS_MAX 100000
#define CAP    64           // max nnz per row; Poisson(10) => P(>64) ~ 0

// ---------------- scratch (__device__ globals; no allocations allowed) ------
__device__ int      g_count[NROWS_MAX];
__device__ unsigned g_bucket[(size_t)NROWS_MAX * CAP];   // (col<<16) | fp16(val)
__device__ uint2    g_wt_h[IN_F * OUT_F / 4];            // Wt[IN][OUT] fp16, as uint2 (4 halves)

// ---------------- kernel 1: transpose+convert W -> fp16, fused counter zero -
// 256 threads/block (32x8), 4 elements per thread; 256 blocks total.
__global__ void __launch_bounds__(256) transpose_kernel(const float* __restrict__ W,
                                                        int n_rows) {
    __shared__ float tile[32][33];
    int tx = threadIdx.x, ty = threadIdx.y;   // tx in [0,32), ty in [0,8)

    // fused: zero per-row counters (65536 threads x 2 covers 100k)
    int flat = (((blockIdx.y * gridDim.x + blockIdx.x) << 8) + (ty << 5) + tx) << 1;
    if (flat < n_rows)     g_count[flat] = 0;
    if (flat + 1 < n_rows) g_count[flat + 1] = 0;

    int x = blockIdx.x * 32 + tx;   // IN index (fast dim of W)
    int y0 = blockIdx.y * 32 + ty;  // OUT index
    #pragma unroll
    for (int k = 0; k < 4; ++k)
        tile[ty + 8 * k][tx] = W[(y0 + 8 * k) * IN_F + x];
    __syncthreads();
    int c0 = blockIdx.x * 32 + ty;  // IN index (row of Wt)
    int o  = blockIdx.y * 32 + tx;  // OUT index (fast dim of Wt)
    #pragma unroll
    for (int k = 0; k < 4; ++k)
        ((__half*)g_wt_h)[(c0 + 8 * k) * OUT_F + o] = __float2half_rn(tile[tx][ty + 8 * k]);
}

// ---------------- kernel 2: scatter nnz into per-row buckets (x4, 4B entries)
__device__ __forceinline__ unsigned pack_entry(int col, float v) {
    return ((unsigned)col << 16) |
           (unsigned)__half_as_ushort(__float2half_rn(v));
}

__global__ void scatter_kernel(const int* __restrict__ rows,
                               const int* __restrict__ cols,
                               const float* __restrict__ vals,
                               int nnz) {
    int t = blockIdx.x * blockDim.x + threadIdx.x;
    int base = t * 4;
    if (base + 3 < nnz) {
        int4   r4 = ((const int4*)rows)[t];
        int4   c4 = ((const int4*)cols)[t];
        float4 v4 = ((const float4*)vals)[t];
        int r, s;
        r = r4.x; s = atomicAdd(&g_count[r], 1);
        if (s < CAP) g_bucket[(size_t)r * CAP + s] = pack_entry(c4.x, v4.x);
        r = r4.y; s = atomicAdd(&g_count[r], 1);
        if (s < CAP) g_bucket[(size_t)r * CAP + s] = pack_entry(c4.y, v4.y);
        r = r4.z; s = atomicAdd(&g_count[r], 1);
        if (s < CAP) g_bucket[(size_t)r * CAP + s] = pack_entry(c4.z, v4.z);
        r = r4.w; s = atomicAdd(&g_count[r], 1);
        if (s < CAP) g_bucket[(size_t)r * CAP + s] = pack_entry(c4.w, v4.w);
    } else {
        for (int i = base; i < nnz; ++i) {
            int r = rows[i];
            int s = atomicAdd(&g_count[r], 1);
            if (s < CAP) g_bucket[(size_t)r * CAP + s] = pack_entry(cols[i], vals[i]);
        }
    }
}

// accumulate a uint2 (= 2 half2) into two half2 accumulators
__device__ __forceinline__ void acc_u2(uint2 w, __half2 v, __half2& aA, __half2& aB) {
    aA = __hfma2(v, *(const __half2*)&w.x, aA);
    aB = __hfma2(v, *(const __half2*)&w.y, aB);
}

// one nnz step from a broadcast packed entry
#define NNZ_STEP_E(e)                                                      \
    {                                                                      \
        unsigned hv_ = __byte_perm((e), 0, 0x1010);                        \
        __half2 v_ = *(const __half2*)&hv_;                                \
        const uint2* p_ = wl + ((e) >> 16) * 64u;                          \
        uint2 wA_ = p_[0], wB_ = p_[32];                                   \
        acc_u2(wA_, v_, a0, a1);                                           \
        acc_u2(wB_, v_, a2, a3);                                           \
    }

// ---------------- kernel 3: one warp per row, LDG.64 weights + HFMA2 --------
// Packed 4B entries: preload of 32 entries = one 128B line (1 wavefront),
// 1 SHFL + 1 PRMT per nnz. Unroll-4 keeps 8 LDG.64 in flight.
__global__ void __launch_bounds__(256) spmm_kernel(const float* __restrict__ bias,
                                                   float* __restrict__ out,
                                                   int n_rows) {
    int gwarp = (blockIdx.x * blockDim.x + threadIdx.x) >> 5;
    int lane  = threadIdx.x & 31;
    if (gwarp >= n_rows) return;
    int r = gwarp;

    int cnt = g_count[r];
    if (cnt > CAP) cnt = CAP;
    const unsigned* bk = g_bucket + (size_t)r * CAP;

    // preload up to 32 packed entries (single 128B line)
    unsigned my = 0u;
    if (lane < cnt) my = bk[lane];

    __half2 a0 = __float2half2_rn(0.f);
    __half2 a1 = a0, a2 = a0, a3 = a0;

    const uint2* wl = g_wt_h + lane;   // + col*64 (+32 for upper half) per access

    int n0 = cnt < 32 ? cnt : 32;
    int j = 0;
    // unroll-4 main loop: 8 LDG.64 in flight
    #pragma unroll 1
    for (; j + 4 <= n0; j += 4) {
        unsigned e0 = __shfl_sync(0xffffffffu, my, j);
        unsigned e1 = __shfl_sync(0xffffffffu, my, j + 1);
        unsigned e2 = __shfl_sync(0xffffffffu, my, j + 2);
        unsigned e3 = __shfl_sync(0xffffffffu, my, j + 3);
        const uint2* p0 = wl + (e0 >> 16) * 64u;
        const uint2* p1 = wl + (e1 >> 16) * 64u;
        const uint2* p2 = wl + (e2 >> 16) * 64u;
        const uint2* p3 = wl + (e3 >> 16) * 64u;
        uint2 w00 = p0[0], w01 = p0[32];
        uint2 w10 = p1[0], w11 = p1[32];
        uint2 w20 = p2[0], w21 = p2[32];
        uint2 w30 = p3[0], w31 = p3[32];
        unsigned hv0 = __byte_perm(e0, 0, 0x1010);
        unsigned hv1 = __byte_perm(e1, 0, 0x1010);
        unsigned hv2 = __byte_perm(e2, 0, 0x1010);
        unsigned hv3 = __byte_perm(e3, 0, 0x1010);
        __half2 v0 = *(const __half2*)&hv0;
        __half2 v1 = *(const __half2*)&hv1;
        __half2 v2 = *(const __half2*)&hv2;
        __half2 v3 = *(const __half2*)&hv3;
        acc_u2(w00, v0, a0, a1); acc_u2(w01, v0, a2, a3);
        acc_u2(w10, v1, a0, a1); acc_u2(w11, v1, a2, a3);
        acc_u2(w20, v2, a0, a1); acc_u2(w21, v2, a2, a3);
        acc_u2(w30, v3, a0, a1); acc_u2(w31, v3, a2, a3);
    }
    // remainder (0-3 nnz)
    #pragma unroll 1
    for (; j < n0; ++j) {
        unsigned e = __shfl_sync(0xffffffffu, my, j);
        NNZ_STEP_E(e);
    }
    // rare tail (cnt > 32)
    #pragma unroll 1
    for (int t = 32; t < cnt; ++t) {
        unsigned e = bk[t];
        NNZ_STEP_E(e);
    }

    // epilogue: fp32 bias add + store, all LDG.128/STG.128
    const float4* b4 = (const float4*)bias;
    float4 bb0 = b4[lane];        // cols 4l..4l+3
    float4 bb1 = b4[lane + 32];   // cols 128+4l..+3
    float2 f0 = __half22float2(a0);
    float2 f1 = __half22float2(a1);
    float2 f2 = __half22float2(a2);
    float2 f3 = __half22float2(a3);
    float4 o0 = make_float4(f0.x + bb0.x, f0.y + bb0.y, f1.x + bb0.z, f1.y + bb0.w);
    float4 o1 = make_float4(f2.x + bb1.x, f2.y + bb1.y, f3.x + bb1.z, f3.y + bb1.w);

    float4* o4 = (float4*)(out + (size_t)r * OUT_F);
    o4[lane]      = o0;
    o4[lane + 32] = o1;
}

// ---------------- launcher ---------------------------------------------------
extern "C" void kernel_launch(void* const* d_in, const int* in_sizes, int n_in,
                              void* d_out, int out_size) {
    const int*   rows   = (const int*)  d_in[0];
    const int*   cols   = (const int*)  d_in[1];
    const float* vals   = (const float*)d_in[2];
    // d_in[3] = n_rows scalar (unused; derive from out_size)
    const float* weight = (const float*)d_in[4];
    const float* bias   = (const float*)d_in[5];

    int nnz    = in_sizes[0];
    int n_rows = out_size / OUT_F;

    transpose_kernel<<<dim3(IN_F / 32, OUT_F / 32), dim3(32, 8)>>>(weight, n_rows);

    int sthreads = (nnz + 3) / 4;
    scatter_kernel<<<(sthreads + 255) / 256, 256>>>(rows, cols, vals, nnz);

    int warps_per_block = 256 / 32;
    int blocks = (n_rows + warps_per_block - 1) / warps_per_block;
    spmm_kernel<<<blocks, 256>>>(bias, (float*)d_out, n_rows);
}